// round 10
// baseline (speedup 1.0000x reference)
#include <cuda_runtime.h>

typedef unsigned int u32;
typedef unsigned long long u64;

#define NB 32
#define NPTS 16384
#define NP 50
#define SUBN 128
#define NIT 30
#define NBUCK 1024
#define BPB 25
#define RRANGE 0.78539816339744830961f

__device__ u32 g_idx[2][SUBN];
__device__ u32 g_p[2][SUBN];
__device__ float g_src[NB][SUBN][3];
__device__ float g_tgt[NB][SUBN][3];
__device__ float g_pop[2][NB][NP][6];
__device__ float g_fit[2][NB][NP];
__device__ unsigned char g_perm[NIT][3][NB][NP];
__device__ unsigned char g_mask[NIT][NB][NP];
__device__ float g_Rt[NB][12];
__device__ int g_bar[NB];

// phased-selection state
__device__ u32 g_bits[2][2][NPTS];     // [array][round]
__device__ u32 g_hist[2][2][NBUCK];
__device__ u32 g_base[2][2][NBUCK+1];
__device__ u32 g_cursor[2][2][NBUCK];
__device__ unsigned char g_need[2][2][NBUCK];
__device__ u32 g_list[2][2][NPTS];

__device__ __forceinline__ u32 rotl32(u32 x, u32 r){ return (x<<r)|(x>>(32u-r)); }
__device__ __forceinline__ void tf2x32(u32 k0,u32 k1,u32 x0,u32 x1,u32&o0,u32&o1){
  u32 k2 = k0 ^ k1 ^ 0x1BD11BDAu;
  x0 += k0; x1 += k1;
#define TFR(r) { x0 += x1; x1 = rotl32(x1,(r)); x1 ^= x0; }
  TFR(13) TFR(15) TFR(26) TFR(6)   x0+=k1; x1+=k2+1u;
  TFR(17) TFR(29) TFR(16) TFR(24)  x0+=k2; x1+=k0+2u;
  TFR(13) TFR(15) TFR(26) TFR(6)   x0+=k0; x1+=k1+3u;
  TFR(17) TFR(29) TFR(16) TFR(24)  x0+=k1; x1+=k2+4u;
  TFR(13) TFR(15) TFR(26) TFR(6)   x0+=k2; x1+=k0+5u;
#undef TFR
  o0=x0; o1=x1;
}
struct Key { u32 a, b; };
__device__ __forceinline__ Key split_p(Key k, u32 j){
  Key r; tf2x32(k.a,k.b,0u,j,r.a,r.b); return r;
}
__device__ __forceinline__ u32 rbits_p(Key k, u32 i){
  u32 o0,o1; tf2x32(k.a,k.b,0u,i,o0,o1); return o0^o1;
}
__device__ __forceinline__ float unif01(Key k, u32 i){
  u32 b = rbits_p(k,i);
  return __fsub_rn(__uint_as_float((b>>9)|0x3f800000u), 1.0f);
}

// ---- packed f32x2 helpers (IEEE rn per lane; bit-identical to scalar) ----
__device__ __forceinline__ u64 pack2(float lo, float hi){
  u64 v; asm("mov.b64 %0, {%1,%2};" : "=l"(v)
             : "r"(__float_as_uint(lo)), "r"(__float_as_uint(hi))); return v;
}
__device__ __forceinline__ void unpack2(u64 v, float& lo, float& hi){
  u32 a,b; asm("mov.b64 {%0,%1}, %2;" : "=r"(a),"=r"(b) : "l"(v));
  lo=__uint_as_float(a); hi=__uint_as_float(b);
}
__device__ __forceinline__ u64 mul2(u64 a, u64 b){
  u64 d; asm("mul.rn.f32x2 %0,%1,%2;" : "=l"(d) : "l"(a),"l"(b)); return d; }
__device__ __forceinline__ u64 add2(u64 a, u64 b){
  u64 d; asm("add.rn.f32x2 %0,%1,%2;" : "=l"(d) : "l"(a),"l"(b)); return d; }
__device__ __forceinline__ u64 fma2_(u64 a, u64 b, u64 c){
  u64 d; asm("fma.rn.f32x2 %0,%1,%2,%3;" : "=l"(d) : "l"(a),"l"(b),"l"(c)); return d; }

// ================= phased exact rank selection =================
__global__ void k_zero(){
  int gid = blockIdx.x*blockDim.x + threadIdx.x;
  u32* h = &g_hist[0][0][0];
  unsigned char* nd = &g_need[0][0][0];
  for(int i=gid; i<2*2*NBUCK; i+=gridDim.x*blockDim.x){ h[i]=0u; nd[i]=0; }
}

// all 4 bit-arrays + histograms
__global__ void k_bits(){
  int gid = blockIdx.x*blockDim.x + threadIdx.x;
  int nth = gridDim.x*blockDim.x;
  Key b42; b42.a=0u; b42.b=42u;
  Key sub[2][2];
  for(int a=0;a<2;a++){
    Key ka = split_p(b42,(u32)a);
    sub[a][0] = split_p(ka,1);               // round-1 shuffle bits
    sub[a][1] = split_p(split_p(ka,0),1);    // round-2 shuffle bits
  }
  for(int idx=gid; idx<4*NPTS; idx+=nth){
    int a = idx/(2*NPTS);
    int r = (idx/NPTS)&1;
    int i = idx%NPTS;
    u32 bits = rbits_p(sub[a][r],(u32)i);
    g_bits[a][r][i] = bits;
    atomicAdd(&g_hist[a][r][bits>>22], 1u);
  }
}

// per-(a,r) bucket scan; cursors; round-2 need flags
__global__ void __launch_bounds__(1024,1) k_scan(){
  __shared__ u32 wsum[32];
  const int a = blockIdx.x>>1, r = blockIdx.x&1;
  const int t = threadIdx.x, lane = t&31, warp = t>>5;
  u32 orig = g_hist[a][r][t]; u32 v = orig;
#pragma unroll
  for(int o=1;o<32;o<<=1){ u32 x=__shfl_up_sync(0xffffffffu,v,o); if(lane>=o) v+=x; }
  if(lane==31) wsum[warp]=v;
  __syncthreads();
  if(warp==0){
    u32 w=wsum[lane];
#pragma unroll
    for(int o=1;o<32;o<<=1){ u32 x=__shfl_up_sync(0xffffffffu,w,o); if(lane>=o) w+=x; }
    wsum[lane]=w;
  }
  __syncthreads();
  u32 incl = v + (warp>0 ? wsum[warp-1] : 0u);
  u32 excl = incl - orig;
  g_base[a][r][t+1]=incl; if(t==0) g_base[a][r][0]=0u;
  g_cursor[a][r][t] = excl;
  if(r==1 && excl < SUBN && orig>0u) g_need[a][1][t]=1;
}

// scatter needed buckets' element indices
__global__ void k_scatter(int r){
  int gid = blockIdx.x*blockDim.x + threadIdx.x;
  int nth = gridDim.x*blockDim.x;
  for(int idx=gid; idx<2*NPTS; idx+=nth){
    int a = idx/NPTS, i = idx%NPTS;
    u32 bits = g_bits[a][r][i];
    u32 b = bits>>22;
    if(g_need[a][r][b]){
      u32 pos = atomicAdd(&g_cursor[a][r][b],1u);
      g_list[a][r][pos] = (u32)i;
    }
  }
}

// rank selection within buckets (stable composite (bits<<14|pos))
__global__ void k_select(int r){
  const int a = blockIdx.x, t = threadIdx.x;
  u32 q = (r==1) ? (u32)t : g_p[a][t];
  int lo=0,hi=NBUCK;
  while(hi-lo>1){ int mid=(lo+hi)>>1; if(g_base[a][r][mid]<=q) lo=mid; else hi=mid; }
  u32 st=g_base[a][r][lo], en=g_base[a][r][lo+1], off=q-st;
  u32 ans=0u;
  for(u32 x=st;x<en;x++){
    u32 m=g_list[a][r][x]; u64 km=((u64)g_bits[a][r][m]<<14)|(u64)m; u32 rk=0;
    for(u32 y=st;y<en;y++){
      u32 o2=g_list[a][r][y]; u64 ko=((u64)g_bits[a][r][o2]<<14)|(u64)o2;
      rk += (ko<km)?1u:0u;
    }
    if(rk==off){ ans=m; break; }
  }
  if(r==1){
    g_p[a][t]=ans;
    // flag the round-1 bucket containing rank 'ans'
    int l2=0,h2=NBUCK;
    while(h2-l2>1){ int mid=(l2+h2)>>1; if(g_base[a][0][mid]<=ans) l2=mid; else h2=mid; }
    g_need[a][0][l2]=1;
  } else {
    g_idx[a][t]=ans;
  }
}

// ---- per-iteration RNG tables (widened to 512 threads) ----
__global__ void k_tables(){
  const int it = blockIdx.x, tid = threadIdx.x;
  Key base; base.a=0u; base.b=42u;
  Key kloop = split_p(base,4);
  Key kit   = split_p(kloop,(u32)it);
  Key ka    = split_p(kit,0);
  Key kb    = split_p(kit,1);
  Key kc    = split_p(kit,2);
  if(tid < 3*NB){
    Key pk  = split_p(ka,(u32)tid);
    Key sub = split_p(pk,1);
    u64 arr[NP];
    for(int i=0;i<NP;i++) arr[i] = ((u64)rbits_p(sub,(u32)i)<<6) | (u64)(u32)i;
    for(int i=1;i<NP;i++){
      u64 v = arr[i]; int j = i-1;
      while(j>=0 && arr[j]>v){ arr[j+1]=arr[j]; j--; }
      arr[j+1]=v;
    }
    int r = tid>>5, b = tid&31;
    for(int i=0;i<NP;i++) g_perm[it][r][b][i] = (unsigned char)(arr[i]&63u);
  }
  Key kr1 = split_p(kc,0);
  Key kr2 = split_p(kc,1);
  for(int f=tid; f<NB*NP; f+=blockDim.x){
    u32 hi = rbits_p(kr1,(u32)f);
    u32 lo = rbits_p(kr2,(u32)f);
    u32 jr = ((hi%6u)*4u + (lo%6u)) % 6u;
    unsigned char m = 0;
    for(int d=0; d<6; d++){
      float u = unif01(kb,(u32)(f*6+d));
      if(u < 0.9f || (u32)d == jr) m |= (unsigned char)(1<<d);
    }
    g_mask[it][f/NP][f%NP] = m;
  }
}

// ---- gather subsets + init population + barrier reset ----
__global__ void k_init(const float* __restrict__ source, const float* __restrict__ target){
  const int gid = blockIdx.x*blockDim.x + threadIdx.x;
  if(gid < NB) g_bar[gid] = 0;
  if(gid < NB*SUBN*3){
    int d = gid%3, i = (gid/3)%SUBN, b = gid/(3*SUBN);
    g_src[b][i][d] = source[((size_t)b*NPTS + g_idx[0][i])*3 + d];
    g_tgt[b][i][d] = target[((size_t)b*NPTS + g_idx[1][i])*3 + d];
  }
  if(gid < NB*NP*3){
    Key base; base.a=0u; base.b=42u;
    Key k2 = split_p(base,2);
    Key k3 = split_p(base,3);
    int d = gid%3, p = (gid/3)%NP, b = gid/(3*NP);
    float r = unif01(k2,(u32)gid);
    float t = unif01(k3,(u32)gid);
    r = fmaxf(-RRANGE, __fadd_rn(__fmul_rn(r, RRANGE+RRANGE), -RRANGE));
    t = fmaxf(-1.0f,   __fadd_rn(__fmul_rn(t, 2.0f), -1.0f));
    if(p==0){ r=0.0f; t=0.0f; }
    g_pop[0][b][p][d]   = r;
    g_pop[0][b][p][d+3] = t;
  }
}

// ---- rotation matrix (identical arithmetic to passing version) ----
__device__ void compute_R(const float* v, float* R){
  float v0=v[0], v1=v[1], v2=v[2];
  float n2 = __fadd_rn(__fadd_rn(__fmul_rn(v0,v0),__fmul_rn(v1,v1)),__fmul_rn(v2,v2));
  float th = __fsqrt_rn(n2);
  float dn = fmaxf(th, 1e-8f);
  float kx = __fdiv_rn(v0,dn), ky = __fdiv_rn(v1,dn), kz = __fdiv_rn(v2,dn);
  float s = sinf(th), c = cosf(th);
  float omc = __fsub_rn(1.0f, c);
  float K[9] = {0.f,-kz,ky,  kz,0.f,-kx,  -ky,kx,0.f};
#pragma unroll
  for(int i=0;i<3;i++)
#pragma unroll
    for(int j=0;j<3;j++){
      float kk = __fmaf_rn(K[i*3+2],K[2*3+j],
                 __fmaf_rn(K[i*3+1],K[1*3+j],
                 __fmul_rn(K[i*3+0],K[0*3+j])));
      float iden = (i==j)?1.0f:0.0f;
      float r = __fadd_rn(__fadd_rn(iden, __fmul_rn(s,K[i*3+j])), __fmul_rn(omc,kk));
      R[i*3+j] = (th < 1e-8f) ? iden : r;
    }
}

struct Sh {
  ulonglong2 tA[SUBN/2];
  ulonglong2 tB[SUBN/2];
  ulonglong2 xA[SUBN/2];
  ulonglong2 xB[SUBN/2];
  ulonglong2 wA[SUBN/2];
  ulonglong2 wB[SUBN/2];
  float ra0[SUBN]; float ca0[SUBN];
  float ra1[SUBN]; float ca1[SUBN];
  float pose[12];
  float R[2][9];
  int imp[2];
};

__device__ __forceinline__ void bbar(int b, int n, int target){
  __syncthreads();
  if(n==0){
    __threadfence();
    atomicAdd(&g_bar[b], 1);
    while(atomicAdd(&g_bar[b], 0) < target) __nanosleep(64);
    __threadfence();
  }
  __syncthreads();
}

// fits valid on thread 0
__device__ void eval_both(Sh& sm, int n, float s0,float s1,float s2,
                          u64 nu0,u64 nu1,u64 nu2,u64 ynb,
                          float& f0, float& f1){
  float x0,x1,x2,xn, w0,w1,w2,wn;
  {
    const float* R = sm.R[0];
    x0 = __fadd_rn(__fmaf_rn(s2,R[2], __fmaf_rn(s1,R[1], __fmul_rn(s0,R[0]))), sm.pose[3]);
    x1 = __fadd_rn(__fmaf_rn(s2,R[5], __fmaf_rn(s1,R[4], __fmul_rn(s0,R[3]))), sm.pose[4]);
    x2 = __fadd_rn(__fmaf_rn(s2,R[8], __fmaf_rn(s1,R[7], __fmul_rn(s0,R[6]))), sm.pose[5]);
    xn = __fadd_rn(__fadd_rn(__fmul_rn(x0,x0),__fmul_rn(x1,x1)),__fmul_rn(x2,x2));
  }
  {
    const float* R = sm.R[1];
    w0 = __fadd_rn(__fmaf_rn(s2,R[2], __fmaf_rn(s1,R[1], __fmul_rn(s0,R[0]))), sm.pose[9]);
    w1 = __fadd_rn(__fmaf_rn(s2,R[5], __fmaf_rn(s1,R[4], __fmul_rn(s0,R[3]))), sm.pose[10]);
    w2 = __fadd_rn(__fmaf_rn(s2,R[8], __fmaf_rn(s1,R[7], __fmul_rn(s0,R[6]))), sm.pose[11]);
    wn = __fadd_rn(__fadd_rn(__fmul_rn(w0,w0),__fmul_rn(w1,w1)),__fmul_rn(w2,w2));
  }
  {
    int mp = n>>1, h = n&1;
    float* pA = (float*)&sm.xA[mp]; float* pB = (float*)&sm.xB[mp];
    pA[h] = x0; pA[2+h] = x1; pB[h] = x2; pB[2+h] = xn;
    float* qA = (float*)&sm.wA[mp]; float* qB = (float*)&sm.wB[mp];
    qA[h] = w0; qA[2+h] = w1; qB[h] = w2; qB[2+h] = wn;
  }
  u64 nx0=pack2(-x0,-x0), nx1=pack2(-x1,-x1), nx2=pack2(-x2,-x2), xnb=pack2(xn,xn);
  u64 nw0=pack2(-w0,-w0), nw1=pack2(-w1,-w1), nw2=pack2(-w2,-w2), wnb=pack2(wn,wn);
  __syncthreads();
  const float INF = __int_as_float(0x7f800000);
  float r0l=INF,r0h=INF, r1l=INF,r1h=INF, c0l=INF,c0h=INF, c1l=INF,c1h=INF;
#pragma unroll 4
  for(int mp=0;mp<SUBN/2;mp++){
    ulonglong2 a  = sm.tA[mp];
    ulonglong2 bb = sm.tB[mp];
    float lo,hi;
    u64 nd0 = fma2_(nx2, bb.x, fma2_(nx1, a.y, mul2(nx0, a.x)));
    unpack2(add2(add2(xnb, bb.y), nd0), lo, hi);
    r0l = fminf(r0l,lo); r0h = fminf(r0h,hi);
    u64 nd1 = fma2_(nw2, bb.x, fma2_(nw1, a.y, mul2(nw0, a.x)));
    unpack2(add2(add2(wnb, bb.y), nd1), lo, hi);
    r1l = fminf(r1l,lo); r1h = fminf(r1h,hi);
    ulonglong2 xa = sm.xA[mp];
    ulonglong2 xb = sm.xB[mp];
    u64 cd0 = fma2_(nu2, xb.x, fma2_(nu1, xa.y, mul2(nu0, xa.x)));
    unpack2(add2(add2(ynb, xb.y), cd0), lo, hi);
    c0l = fminf(c0l,lo); c0h = fminf(c0h,hi);
    ulonglong2 wa = sm.wA[mp];
    ulonglong2 wb = sm.wB[mp];
    u64 cd1 = fma2_(nu2, wb.x, fma2_(nu1, wa.y, mul2(nu0, wa.x)));
    unpack2(add2(add2(ynb, wb.y), cd1), lo, hi);
    c1l = fminf(c1l,lo); c1h = fminf(c1h,hi);
  }
  sm.ra0[n] = fmaxf(fminf(r0l,r0h), 0.0f);
  sm.ca0[n] = fmaxf(fminf(c0l,c0h), 0.0f);
  sm.ra1[n] = fmaxf(fminf(r1l,r1h), 0.0f);
  sm.ca1[n] = fmaxf(fminf(c1l,c1h), 0.0f);
  __syncthreads();
  f0 = 0.0f; f1 = 0.0f;
  if(n < 32){
    float pr0 = __fadd_rn(__fadd_rn(__fadd_rn(sm.ra0[n], sm.ra0[n+32]), sm.ra0[n+64]), sm.ra0[n+96]);
    float pc0 = __fadd_rn(__fadd_rn(__fadd_rn(sm.ca0[n], sm.ca0[n+32]), sm.ca0[n+64]), sm.ca0[n+96]);
    float pr1 = __fadd_rn(__fadd_rn(__fadd_rn(sm.ra1[n], sm.ra1[n+32]), sm.ra1[n+64]), sm.ra1[n+96]);
    float pc1 = __fadd_rn(__fadd_rn(__fadd_rn(sm.ca1[n], sm.ca1[n+32]), sm.ca1[n+64]), sm.ca1[n+96]);
#pragma unroll
    for(int o=16;o>0;o>>=1){
      pr0 = __fadd_rn(pr0, __shfl_down_sync(0xffffffffu, pr0, o));
      pc0 = __fadd_rn(pc0, __shfl_down_sync(0xffffffffu, pc0, o));
      pr1 = __fadd_rn(pr1, __shfl_down_sync(0xffffffffu, pr1, o));
      pc1 = __fadd_rn(pc1, __shfl_down_sync(0xffffffffu, pc1, o));
    }
    f0 = __fadd_rn(__fmul_rn(pr0,0.0078125f), __fmul_rn(pc0,0.0078125f));
    f1 = __fadd_rn(__fmul_rn(pr1,0.0078125f), __fmul_rn(pc1,0.0078125f));
  }
}

// ---- persistent DE kernel: 2 particles per block, fused eval ----
__global__ void __launch_bounds__(SUBN, 6)
k_de(const float* __restrict__ source, float* __restrict__ out){
  __shared__ Sh sm;
  const int b = blockIdx.x / BPB, q = blockIdx.x % BPB, n = threadIdx.x;
  const int p0 = 2*q, p1 = 2*q+1;

  const float s0=g_src[b][n][0], s1=g_src[b][n][1], s2=g_src[b][n][2];
  const float u0=g_tgt[b][n][0], u1=g_tgt[b][n][1], u2=g_tgt[b][n][2];
  const float ynv = __fadd_rn(__fadd_rn(__fmul_rn(u0,u0),__fmul_rn(u1,u1)),__fmul_rn(u2,u2));
  const float u0d=__fadd_rn(u0,u0), u1d=__fadd_rn(u1,u1), u2d=__fadd_rn(u2,u2);
  {
    int mp = n>>1, h = n&1;
    float* pA = (float*)&sm.tA[mp]; float* pB = (float*)&sm.tB[mp];
    pA[h] = u0d; pA[2+h] = u1d; pB[h] = u2d; pB[2+h] = ynv;
  }
  const u64 nu0 = pack2(-u0d,-u0d), nu1 = pack2(-u1d,-u1d), nu2 = pack2(-u2d,-u2d);
  const u64 ynb = pack2(ynv,ynv);

  if(n<2){
    float* ps = sm.pose + 6*n;
    for(int d=0;d<6;d++) ps[d] = g_pop[0][b][p0+n][d];
    compute_R(ps, sm.R[n]);
  }
  __syncthreads();
  float f0,f1;
  eval_both(sm,n,s0,s1,s2,nu0,nu1,nu2,ynb,f0,f1);
  if(n==0){ g_fit[0][b][p0]=f0; g_fit[0][b][p1]=f1; }
  bbar(b,n,BPB*1);

  int sb = 0;
  for(int it=0; it<NIT; ++it){
    const int db = sb^1;
    if(n<2){
      const int p = p0 + n;
      float* ps = sm.pose + 6*n;
      int r1 = g_perm[it][0][b][p], r2 = g_perm[it][1][b][p], r3 = g_perm[it][2][b][p];
      unsigned char m = g_mask[it][b][p];
#pragma unroll
      for(int d=0;d<6;d++){
        float mu = __fadd_rn(g_pop[sb][b][r1][d],
                   __fmul_rn(0.8f, __fsub_rn(g_pop[sb][b][r2][d], g_pop[sb][b][r3][d])));
        float lim = (d<3) ? RRANGE : 1.0f;
        mu = fminf(fmaxf(mu, -lim), lim);
        ps[d] = ((m>>d)&1) ? mu : g_pop[sb][b][p][d];
      }
      compute_R(ps, sm.R[n]);
    }
    __syncthreads();
    float tf0,tf1;
    eval_both(sm,n,s0,s1,s2,nu0,nu1,nu2,ynb,tf0,tf1);
    if(n==0){
      float of0 = g_fit[sb][b][p0], of1 = g_fit[sb][b][p1];
      sm.imp[0] = (tf0 < of0);
      sm.imp[1] = (tf1 < of1);
      g_fit[db][b][p0] = sm.imp[0] ? tf0 : of0;
      g_fit[db][b][p1] = sm.imp[1] ? tf1 : of1;
    }
    __syncthreads();
    if(n<12){
      const int pp = n/6, d = n%6, p = p0 + pp;
      g_pop[db][b][p][d] = sm.imp[pp] ? sm.pose[n] : g_pop[sb][b][p][d];
    }
    bbar(b,n,BPB*(it+2));
    sb = db;
  }

  if(q==0 && n==0){
    float best = g_fit[sb][b][0]; int bi = 0;
    for(int pq=1;pq<NP;pq++){ float ff = g_fit[sb][b][pq]; if(ff < best){ best=ff; bi=pq; } }
    float pose[6];
    for(int d=0;d<6;d++) pose[d] = g_pop[sb][b][bi][d];
    float R[9]; compute_R(pose, R);
    for(int i=0;i<9;i++){ out[b*9+i] = R[i]; g_Rt[b][i] = R[i]; }
    for(int k=0;k<3;k++){ out[NB*9 + b*3 + k] = pose[3+k]; g_Rt[b][9+k] = pose[3+k]; }
  }
  bbar(b,n,BPB*(NIT+2));

  float Rt[12];
#pragma unroll
  for(int i=0;i<12;i++) Rt[i] = g_Rt[b][i];
  const int per = (NPTS + BPB - 1)/BPB;
  const int hi  = min((q+1)*per, NPTS);
  for(int i = q*per + n; i < hi; i += SUBN){
    const float* sp = source + ((size_t)b*NPTS + i)*3;
    float a0=sp[0], a1=sp[1], a2=sp[2];
    float* op = out + NB*12 + ((size_t)b*NPTS + i)*3;
#pragma unroll
    for(int k=0;k<3;k++){
      float dot = __fmaf_rn(a2, Rt[k*3+2],
                  __fmaf_rn(a1, Rt[k*3+1],
                  __fmul_rn(a0, Rt[k*3+0])));
      op[k] = __fadd_rn(dot, Rt[9+k]);
    }
  }
}

extern "C" void kernel_launch(void* const* d_in, const int* in_sizes, int n_in,
                              void* d_out, int out_size){
  (void)in_sizes; (void)n_in; (void)out_size;
  const float* source = (const float*)d_in[0];
  const float* target = (const float*)d_in[1];
  float* out = (float*)d_out;

  k_zero<<<4, 1024>>>();
  k_bits<<<64, 256>>>();
  k_scan<<<4, 1024>>>();
  k_scatter<<<64, 256>>>(1);
  k_select<<<2, SUBN>>>(1);
  k_scatter<<<64, 256>>>(0);
  k_select<<<2, SUBN>>>(0);
  k_tables<<<NIT, 512>>>();
  k_init<<<(NB*SUBN*3 + 255)/256, 256>>>(source, target);
  k_de<<<NB*BPB, SUBN>>>(source, out);
}

// round 11
// speedup vs baseline: 1.1392x; 1.1392x over previous
#include <cuda_runtime.h>

typedef unsigned int u32;
typedef unsigned long long u64;

#define NB 32
#define NPTS 16384
#define NP 50
#define SUBN 128
#define NIT 30
#define NBUCK 1024
#define BPB 25
#define RRANGE 0.78539816339744830961f

__device__ u32 g_idx[2][SUBN];
__device__ u32 g_p[2][SUBN];
__device__ float g_pop[2][NB][NP][6];
__device__ float g_fit[2][NB][NP];
__device__ unsigned char g_perm[NIT][3][NB][NP];
__device__ unsigned char g_mask[NIT][NB][NP];
__device__ float g_Rt[NB][12];
__device__ int g_bar[NB];

__device__ __forceinline__ u32 rotl32(u32 x, u32 r){ return (x<<r)|(x>>(32u-r)); }
__device__ __forceinline__ void tf2x32(u32 k0,u32 k1,u32 x0,u32 x1,u32&o0,u32&o1){
  u32 k2 = k0 ^ k1 ^ 0x1BD11BDAu;
  x0 += k0; x1 += k1;
#define TFR(r) { x0 += x1; x1 = rotl32(x1,(r)); x1 ^= x0; }
  TFR(13) TFR(15) TFR(26) TFR(6)   x0+=k1; x1+=k2+1u;
  TFR(17) TFR(29) TFR(16) TFR(24)  x0+=k2; x1+=k0+2u;
  TFR(13) TFR(15) TFR(26) TFR(6)   x0+=k0; x1+=k1+3u;
  TFR(17) TFR(29) TFR(16) TFR(24)  x0+=k1; x1+=k2+4u;
  TFR(13) TFR(15) TFR(26) TFR(6)   x0+=k2; x1+=k0+5u;
#undef TFR
  o0=x0; o1=x1;
}
struct Key { u32 a, b; };
__device__ __forceinline__ Key split_p(Key k, u32 j){
  Key r; tf2x32(k.a,k.b,0u,j,r.a,r.b); return r;
}
__device__ __forceinline__ u32 rbits_p(Key k, u32 i){
  u32 o0,o1; tf2x32(k.a,k.b,0u,i,o0,o1); return o0^o1;
}
__device__ __forceinline__ float unif01(Key k, u32 i){
  u32 b = rbits_p(k,i);
  return __fsub_rn(__uint_as_float((b>>9)|0x3f800000u), 1.0f);
}

// ---- packed f32x2 helpers (IEEE rn per lane; bit-identical to scalar) ----
__device__ __forceinline__ u64 pack2(float lo, float hi){
  u64 v; asm("mov.b64 %0, {%1,%2};" : "=l"(v)
             : "r"(__float_as_uint(lo)), "r"(__float_as_uint(hi))); return v;
}
__device__ __forceinline__ void unpack2(u64 v, float& lo, float& hi){
  u32 a,b; asm("mov.b64 {%0,%1}, %2;" : "=r"(a),"=r"(b) : "l"(v));
  lo=__uint_as_float(a); hi=__uint_as_float(b);
}
__device__ __forceinline__ u64 mul2(u64 a, u64 b){
  u64 d; asm("mul.rn.f32x2 %0,%1,%2;" : "=l"(d) : "l"(a),"l"(b)); return d; }
__device__ __forceinline__ u64 add2(u64 a, u64 b){
  u64 d; asm("add.rn.f32x2 %0,%1,%2;" : "=l"(d) : "l"(a),"l"(b)); return d; }
__device__ __forceinline__ u64 fma2_(u64 a, u64 b, u64 c){
  u64 d; asm("fma.rn.f32x2 %0,%1,%2,%3;" : "=l"(d) : "l"(a),"l"(b),"l"(c)); return d; }

// ================= in-block exact rank selection (proven R8 code) =================
struct SelSm {
  u32 bits[NPTS];
  u32 list[NPTS];
  u32 hist[NBUCK];
  u32 base[NBUCK+1];
  u32 cursor[NBUCK];
  u32 wsum[32];
  unsigned char needed[NBUCK];
};

__device__ void do_select(SelSm& s, Key sub, const u32* req, u32* out){
  const int t = threadIdx.x, lane = t&31, warp = t>>5;
  for(int i=t;i<NPTS;i+=1024) s.bits[i] = rbits_p(sub,(u32)i);
  s.hist[t] = 0u; s.needed[t] = 0;
  __syncthreads();
  for(int i=t;i<NPTS;i+=1024) atomicAdd(&s.hist[s.bits[i]>>22], 1u);
  __syncthreads();
  u32 orig = s.hist[t]; u32 v = orig;
#pragma unroll
  for(int o=1;o<32;o<<=1){ u32 x=__shfl_up_sync(0xffffffffu,v,o); if(lane>=o) v+=x; }
  if(lane==31) s.wsum[warp]=v;
  __syncthreads();
  if(warp==0){
    u32 w=s.wsum[lane];
#pragma unroll
    for(int o=1;o<32;o<<=1){ u32 x=__shfl_up_sync(0xffffffffu,w,o); if(lane>=o) w+=x; }
    s.wsum[lane]=w;
  }
  __syncthreads();
  u32 incl = v + (warp>0 ? s.wsum[warp-1] : 0u);
  s.base[t+1]=incl; if(t==0) s.base[0]=0u;
  s.cursor[t] = incl - orig;
  __syncthreads();
  if(t<SUBN){
    u32 q = req ? req[t] : (u32)t;
    int lo=0,hi=NBUCK;
    while(hi-lo>1){ int mid=(lo+hi)>>1; if(s.base[mid]<=q) lo=mid; else hi=mid; }
    s.needed[lo]=1;
  }
  __syncthreads();
  for(int i=t;i<NPTS;i+=1024){
    u32 b = s.bits[i]>>22;
    if(s.needed[b]){ u32 pos=atomicAdd(&s.cursor[b],1u); s.list[pos]=(u32)i; }
  }
  __syncthreads();
  if(t<SUBN){
    u32 q = req ? req[t] : (u32)t;
    int lo=0,hi=NBUCK;
    while(hi-lo>1){ int mid=(lo+hi)>>1; if(s.base[mid]<=q) lo=mid; else hi=mid; }
    u32 st=s.base[lo], en=s.base[lo+1], off=q-st;
    u32 ans=0u;
    for(u32 x=st;x<en;x++){
      u32 m=s.list[x]; u64 km=((u64)s.bits[m]<<14)|(u64)m; u32 rk=0;
      for(u32 y=st;y<en;y++){
        u32 o2=s.list[y]; u64 ko=((u64)s.bits[o2]<<14)|(u64)o2;
        rk += (ko<km)?1u:0u;
      }
      if(rk==off){ ans=m; break; }
    }
    out[t]=ans;
  }
}

// ---- ONE preamble kernel: blocks 0-1 = selection (both rounds), blocks 2.. = tables ----
__global__ void __launch_bounds__(1024,1) k_pre(){
  Key b42; b42.a=0u; b42.b=42u;
  if(blockIdx.x < 2){
    extern __shared__ char smraw[];
    SelSm& s = *reinterpret_cast<SelSm*>(smraw);
    const int a = blockIdx.x;
    if(a==0 && threadIdx.x < NB) g_bar[threadIdx.x] = 0;
    Key ka   = split_p(b42,(u32)a);
    Key sub2 = split_p(split_p(ka,0),1);   // round-2 shuffle bits
    Key sub1 = split_p(ka,1);              // round-1 shuffle bits
    do_select(s, sub2, nullptr, g_p[a]);   // ranks 0..127 of round 2 -> positions
    __syncthreads();
    do_select(s, sub1, g_p[a], g_idx[a]);  // elements at those round-1 ranks
    return;
  }
  // ---- tables for iteration it ----
  const int it = blockIdx.x - 2, tid = threadIdx.x;
  Key kloop = split_p(b42,4);
  Key kit   = split_p(kloop,(u32)it);
  Key ka    = split_p(kit,0);
  Key kb    = split_p(kit,1);
  Key kc    = split_p(kit,2);
  if(tid < 3*NB){
    Key pk  = split_p(ka,(u32)tid);
    Key sub = split_p(pk,1);
    u64 arr[NP];
    for(int i=0;i<NP;i++) arr[i] = ((u64)rbits_p(sub,(u32)i)<<6) | (u64)(u32)i;
    for(int i=1;i<NP;i++){
      u64 v = arr[i]; int j = i-1;
      while(j>=0 && arr[j]>v){ arr[j+1]=arr[j]; j--; }
      arr[j+1]=v;
    }
    int r = tid>>5, b = tid&31;
    for(int i=0;i<NP;i++) g_perm[it][r][b][i] = (unsigned char)(arr[i]&63u);
  }
  Key kr1 = split_p(kc,0);
  Key kr2 = split_p(kc,1);
  for(int f=tid; f<NB*NP; f+=blockDim.x){
    u32 hi = rbits_p(kr1,(u32)f);
    u32 lo = rbits_p(kr2,(u32)f);
    u32 jr = ((hi%6u)*4u + (lo%6u)) % 6u;
    unsigned char m = 0;
    for(int d=0; d<6; d++){
      float u = unif01(kb,(u32)(f*6+d));
      if(u < 0.9f || (u32)d == jr) m |= (unsigned char)(1<<d);
    }
    g_mask[it][f/NP][f%NP] = m;
  }
}

// ---- rotation matrix (identical arithmetic to passing version) ----
__device__ void compute_R(const float* v, float* R){
  float v0=v[0], v1=v[1], v2=v[2];
  float n2 = __fadd_rn(__fadd_rn(__fmul_rn(v0,v0),__fmul_rn(v1,v1)),__fmul_rn(v2,v2));
  float th = __fsqrt_rn(n2);
  float dn = fmaxf(th, 1e-8f);
  float kx = __fdiv_rn(v0,dn), ky = __fdiv_rn(v1,dn), kz = __fdiv_rn(v2,dn);
  float s = sinf(th), c = cosf(th);
  float omc = __fsub_rn(1.0f, c);
  float K[9] = {0.f,-kz,ky,  kz,0.f,-kx,  -ky,kx,0.f};
#pragma unroll
  for(int i=0;i<3;i++)
#pragma unroll
    for(int j=0;j<3;j++){
      float kk = __fmaf_rn(K[i*3+2],K[2*3+j],
                 __fmaf_rn(K[i*3+1],K[1*3+j],
                 __fmul_rn(K[i*3+0],K[0*3+j])));
      float iden = (i==j)?1.0f:0.0f;
      float r = __fadd_rn(__fadd_rn(iden, __fmul_rn(s,K[i*3+j])), __fmul_rn(omc,kk));
      R[i*3+j] = (th < 1e-8f) ? iden : r;
    }
}

struct Sh {
  ulonglong2 tA[SUBN/2];
  ulonglong2 tB[SUBN/2];
  ulonglong2 xA[SUBN/2];
  ulonglong2 xB[SUBN/2];
  ulonglong2 wA[SUBN/2];
  ulonglong2 wB[SUBN/2];
  float ra0[SUBN]; float ca0[SUBN];
  float ra1[SUBN]; float ca1[SUBN];
  float pose[12];
  float R[2][9];
  int imp[2];
};

__device__ __forceinline__ void bbar(int b, int n, int target){
  __syncthreads();
  if(n==0){
    __threadfence();
    atomicAdd(&g_bar[b], 1);
    while(atomicAdd(&g_bar[b], 0) < target) __nanosleep(64);
    __threadfence();
  }
  __syncthreads();
}

// fits valid on thread 0
__device__ void eval_both(Sh& sm, int n, float s0,float s1,float s2,
                          u64 nu0,u64 nu1,u64 nu2,u64 ynb,
                          float& f0, float& f1){
  float x0,x1,x2,xn, w0,w1,w2,wn;
  {
    const float* R = sm.R[0];
    x0 = __fadd_rn(__fmaf_rn(s2,R[2], __fmaf_rn(s1,R[1], __fmul_rn(s0,R[0]))), sm.pose[3]);
    x1 = __fadd_rn(__fmaf_rn(s2,R[5], __fmaf_rn(s1,R[4], __fmul_rn(s0,R[3]))), sm.pose[4]);
    x2 = __fadd_rn(__fmaf_rn(s2,R[8], __fmaf_rn(s1,R[7], __fmul_rn(s0,R[6]))), sm.pose[5]);
    xn = __fadd_rn(__fadd_rn(__fmul_rn(x0,x0),__fmul_rn(x1,x1)),__fmul_rn(x2,x2));
  }
  {
    const float* R = sm.R[1];
    w0 = __fadd_rn(__fmaf_rn(s2,R[2], __fmaf_rn(s1,R[1], __fmul_rn(s0,R[0]))), sm.pose[9]);
    w1 = __fadd_rn(__fmaf_rn(s2,R[5], __fmaf_rn(s1,R[4], __fmul_rn(s0,R[3]))), sm.pose[10]);
    w2 = __fadd_rn(__fmaf_rn(s2,R[8], __fmaf_rn(s1,R[7], __fmul_rn(s0,R[6]))), sm.pose[11]);
    wn = __fadd_rn(__fadd_rn(__fmul_rn(w0,w0),__fmul_rn(w1,w1)),__fmul_rn(w2,w2));
  }
  {
    int mp = n>>1, h = n&1;
    float* pA = (float*)&sm.xA[mp]; float* pB = (float*)&sm.xB[mp];
    pA[h] = x0; pA[2+h] = x1; pB[h] = x2; pB[2+h] = xn;
    float* qA = (float*)&sm.wA[mp]; float* qB = (float*)&sm.wB[mp];
    qA[h] = w0; qA[2+h] = w1; qB[h] = w2; qB[2+h] = wn;
  }
  u64 nx0=pack2(-x0,-x0), nx1=pack2(-x1,-x1), nx2=pack2(-x2,-x2), xnb=pack2(xn,xn);
  u64 nw0=pack2(-w0,-w0), nw1=pack2(-w1,-w1), nw2=pack2(-w2,-w2), wnb=pack2(wn,wn);
  __syncthreads();
  const float INF = __int_as_float(0x7f800000);
  float r0l=INF,r0h=INF, r1l=INF,r1h=INF, c0l=INF,c0h=INF, c1l=INF,c1h=INF;
#pragma unroll 4
  for(int mp=0;mp<SUBN/2;mp++){
    ulonglong2 a  = sm.tA[mp];
    ulonglong2 bb = sm.tB[mp];
    float lo,hi;
    u64 nd0 = fma2_(nx2, bb.x, fma2_(nx1, a.y, mul2(nx0, a.x)));
    unpack2(add2(add2(xnb, bb.y), nd0), lo, hi);
    r0l = fminf(r0l,lo); r0h = fminf(r0h,hi);
    u64 nd1 = fma2_(nw2, bb.x, fma2_(nw1, a.y, mul2(nw0, a.x)));
    unpack2(add2(add2(wnb, bb.y), nd1), lo, hi);
    r1l = fminf(r1l,lo); r1h = fminf(r1h,hi);
    ulonglong2 xa = sm.xA[mp];
    ulonglong2 xb = sm.xB[mp];
    u64 cd0 = fma2_(nu2, xb.x, fma2_(nu1, xa.y, mul2(nu0, xa.x)));
    unpack2(add2(add2(ynb, xb.y), cd0), lo, hi);
    c0l = fminf(c0l,lo); c0h = fminf(c0h,hi);
    ulonglong2 wa = sm.wA[mp];
    ulonglong2 wb = sm.wB[mp];
    u64 cd1 = fma2_(nu2, wb.x, fma2_(nu1, wa.y, mul2(nu0, wa.x)));
    unpack2(add2(add2(ynb, wb.y), cd1), lo, hi);
    c1l = fminf(c1l,lo); c1h = fminf(c1h,hi);
  }
  sm.ra0[n] = fmaxf(fminf(r0l,r0h), 0.0f);
  sm.ca0[n] = fmaxf(fminf(c0l,c0h), 0.0f);
  sm.ra1[n] = fmaxf(fminf(r1l,r1h), 0.0f);
  sm.ca1[n] = fmaxf(fminf(c1l,c1h), 0.0f);
  __syncthreads();
  f0 = 0.0f; f1 = 0.0f;
  if(n < 32){
    float pr0 = __fadd_rn(__fadd_rn(__fadd_rn(sm.ra0[n], sm.ra0[n+32]), sm.ra0[n+64]), sm.ra0[n+96]);
    float pc0 = __fadd_rn(__fadd_rn(__fadd_rn(sm.ca0[n], sm.ca0[n+32]), sm.ca0[n+64]), sm.ca0[n+96]);
    float pr1 = __fadd_rn(__fadd_rn(__fadd_rn(sm.ra1[n], sm.ra1[n+32]), sm.ra1[n+64]), sm.ra1[n+96]);
    float pc1 = __fadd_rn(__fadd_rn(__fadd_rn(sm.ca1[n], sm.ca1[n+32]), sm.ca1[n+64]), sm.ca1[n+96]);
#pragma unroll
    for(int o=16;o>0;o>>=1){
      pr0 = __fadd_rn(pr0, __shfl_down_sync(0xffffffffu, pr0, o));
      pc0 = __fadd_rn(pc0, __shfl_down_sync(0xffffffffu, pc0, o));
      pr1 = __fadd_rn(pr1, __shfl_down_sync(0xffffffffu, pr1, o));
      pc1 = __fadd_rn(pc1, __shfl_down_sync(0xffffffffu, pc1, o));
    }
    f0 = __fadd_rn(__fmul_rn(pr0,0.0078125f), __fmul_rn(pc0,0.0078125f));
    f1 = __fadd_rn(__fmul_rn(pr1,0.0078125f), __fmul_rn(pc1,0.0078125f));
  }
}

// ---- persistent DE kernel: absorbs init (gather + initial pop) ----
__global__ void __launch_bounds__(SUBN, 6)
k_de(const float* __restrict__ source, const float* __restrict__ target,
     float* __restrict__ out){
  __shared__ Sh sm;
  const int b = blockIdx.x / BPB, q = blockIdx.x % BPB, n = threadIdx.x;
  const int p0 = 2*q, p1 = 2*q+1;

  // gather subsampled points directly (same values as old k_init path)
  const size_t bs = (size_t)b*NPTS;
  const u32 is = g_idx[0][n], itg = g_idx[1][n];
  const float s0=source[(bs+is)*3+0], s1=source[(bs+is)*3+1], s2=source[(bs+is)*3+2];
  const float u0=target[(bs+itg)*3+0], u1=target[(bs+itg)*3+1], u2=target[(bs+itg)*3+2];
  const float ynv = __fadd_rn(__fadd_rn(__fmul_rn(u0,u0),__fmul_rn(u1,u1)),__fmul_rn(u2,u2));
  const float u0d=__fadd_rn(u0,u0), u1d=__fadd_rn(u1,u1), u2d=__fadd_rn(u2,u2);
  {
    int mp = n>>1, h = n&1;
    float* pA = (float*)&sm.tA[mp]; float* pB = (float*)&sm.tB[mp];
    pA[h] = u0d; pA[2+h] = u1d; pB[h] = u2d; pB[2+h] = ynv;
  }
  const u64 nu0 = pack2(-u0d,-u0d), nu1 = pack2(-u1d,-u1d), nu2 = pack2(-u2d,-u2d);
  const u64 ynb = pack2(ynv,ynv);

  // initial poses computed from RNG (identical sequence to old k_init)
  if(n<2){
    Key b42; b42.a=0u; b42.b=42u;
    Key k2 = split_p(b42,2);
    Key k3 = split_p(b42,3);
    const int p = p0 + n;
    float* ps = sm.pose + 6*n;
#pragma unroll
    for(int d=0;d<3;d++){
      u32 gid = (u32)((b*NP + p)*3 + d);
      float r = unif01(k2,gid);
      float t = unif01(k3,gid);
      r = fmaxf(-RRANGE, __fadd_rn(__fmul_rn(r, RRANGE+RRANGE), -RRANGE));
      t = fmaxf(-1.0f,   __fadd_rn(__fmul_rn(t, 2.0f), -1.0f));
      if(p==0){ r=0.0f; t=0.0f; }
      ps[d] = r; ps[d+3] = t;
      g_pop[0][b][p][d] = r; g_pop[0][b][p][d+3] = t;
    }
    compute_R(ps, sm.R[n]);
  }
  __syncthreads();
  float f0,f1;
  eval_both(sm,n,s0,s1,s2,nu0,nu1,nu2,ynb,f0,f1);
  if(n==0){ g_fit[0][b][p0]=f0; g_fit[0][b][p1]=f1; }
  bbar(b,n,BPB*1);

  int sb = 0;
  for(int it=0; it<NIT; ++it){
    const int db = sb^1;
    if(n<2){
      const int p = p0 + n;
      float* ps = sm.pose + 6*n;
      int r1 = g_perm[it][0][b][p], r2 = g_perm[it][1][b][p], r3 = g_perm[it][2][b][p];
      unsigned char m = g_mask[it][b][p];
#pragma unroll
      for(int d=0;d<6;d++){
        float mu = __fadd_rn(g_pop[sb][b][r1][d],
                   __fmul_rn(0.8f, __fsub_rn(g_pop[sb][b][r2][d], g_pop[sb][b][r3][d])));
        float lim = (d<3) ? RRANGE : 1.0f;
        mu = fminf(fmaxf(mu, -lim), lim);
        ps[d] = ((m>>d)&1) ? mu : g_pop[sb][b][p][d];
      }
      compute_R(ps, sm.R[n]);
    }
    __syncthreads();
    float tf0,tf1;
    eval_both(sm,n,s0,s1,s2,nu0,nu1,nu2,ynb,tf0,tf1);
    if(n==0){
      float of0 = g_fit[sb][b][p0], of1 = g_fit[sb][b][p1];
      sm.imp[0] = (tf0 < of0);
      sm.imp[1] = (tf1 < of1);
      g_fit[db][b][p0] = sm.imp[0] ? tf0 : of0;
      g_fit[db][b][p1] = sm.imp[1] ? tf1 : of1;
    }
    __syncthreads();
    if(n<12){
      const int pp = n/6, d = n%6, p = p0 + pp;
      g_pop[db][b][p][d] = sm.imp[pp] ? sm.pose[n] : g_pop[sb][b][p][d];
    }
    bbar(b,n,BPB*(it+2));
    sb = db;
  }

  if(q==0 && n==0){
    float best = g_fit[sb][b][0]; int bi = 0;
    for(int pq=1;pq<NP;pq++){ float ff = g_fit[sb][b][pq]; if(ff < best){ best=ff; bi=pq; } }
    float pose[6];
    for(int d=0;d<6;d++) pose[d] = g_pop[sb][b][bi][d];
    float R[9]; compute_R(pose, R);
    for(int i=0;i<9;i++){ out[b*9+i] = R[i]; g_Rt[b][i] = R[i]; }
    for(int k=0;k<3;k++){ out[NB*9 + b*3 + k] = pose[3+k]; g_Rt[b][9+k] = pose[3+k]; }
  }
  bbar(b,n,BPB*(NIT+2));

  float Rt[12];
#pragma unroll
  for(int i=0;i<12;i++) Rt[i] = g_Rt[b][i];
  const int per = (NPTS + BPB - 1)/BPB;
  const int hi  = min((q+1)*per, NPTS);
  for(int i = q*per + n; i < hi; i += SUBN){
    const float* sp = source + (bs + i)*3;
    float a0=sp[0], a1=sp[1], a2=sp[2];
    float* op = out + NB*12 + (bs + i)*3;
#pragma unroll
    for(int k=0;k<3;k++){
      float dot = __fmaf_rn(a2, Rt[k*3+2],
                  __fmaf_rn(a1, Rt[k*3+1],
                  __fmul_rn(a0, Rt[k*3+0])));
      op[k] = __fadd_rn(dot, Rt[9+k]);
    }
  }
}

extern "C" void kernel_launch(void* const* d_in, const int* in_sizes, int n_in,
                              void* d_out, int out_size){
  (void)in_sizes; (void)n_in; (void)out_size;
  const float* source = (const float*)d_in[0];
  const float* target = (const float*)d_in[1];
  float* out = (float*)d_out;

  cudaFuncSetAttribute(k_pre, cudaFuncAttributeMaxDynamicSharedMemorySize, (int)sizeof(SelSm));
  k_pre<<<2 + NIT, 1024, sizeof(SelSm)>>>();
  k_de<<<NB*BPB, SUBN>>>(source, target, out);
}